// round 8
// baseline (speedup 1.0000x reference)
#include <cuda_runtime.h>

// IntegrableMLP forward + VJP, neuron-pair f32x2 packing, 2 elements/thread
// (R6 math, unchanged tables). R7: layer-FUSED structure to cut the register
// peak (~168 -> ~120): layer-0 outputs feed layer-1 accumulators immediately,
// layer-1 outputs feed layer-2 immediately, and u0 is folded directly into the
// output accumulators (chunked to bound accumulator count). d0/d1 spill to
// dynamic shared ([slot][tid]). 224-thread blocks, __launch_bounds__(224,2)
// -> 14 warps/SM (was 12) and regs <= 146.

#define N0 32
#define N1 32
#define N2 16

typedef unsigned long long ull;

#define FMA2(d, a, b, c) asm("fma.rn.f32x2 %0, %1, %2, %3;" : "=l"(d) : "l"(a), "l"(b), "l"(c))
#define MUL2(d, a, b)    asm("mul.rn.f32x2 %0, %1, %2;"     : "=l"(d) : "l"(a), "l"(b))
#define PACK2(d, lo, hi)   asm("mov.b64 %0, {%1, %2};" : "=l"(d) : "f"(lo), "f"(hi))
#define UNPACK2(lo, hi, s) asm("mov.b64 {%0, %1}, %2;" : "=f"(lo), "=f"(hi) : "l"(s))

__device__ __forceinline__ ull dup_lo(ull p) {
    unsigned lo = (unsigned)p;
    ull r; asm("mov.b64 %0, {%1, %1};" : "=l"(r) : "r"(lo)); return r;
}
__device__ __forceinline__ ull dup_hi(ull p) {
    unsigned hi = (unsigned)(p >> 32);
    ull r; asm("mov.b64 %0, {%1, %1};" : "=l"(r) : "r"(hi)); return r;
}
__device__ __forceinline__ ull packf(float lo, float hi) {
    ull r; PACK2(r, lo, hi); return r;
}

struct __align__(16) ConstTables {
    ull w0c[2][N0 / 2];     // [i][p] = (W0[2p][i], W0[2p+1][i])
    ull b0p[N0 / 2];
    ull w1f[N0][N1 / 2];    // [k][p] = (W1[2p][k], W1[2p+1][k])
    ull b1p[N1 / 2];
    ull w2f[N1][N2 / 2];    // [k][p] = (W2[2p][k], W2[2p+1][k])
    ull b2p[N2 / 2];
    ull vp[N2 / 2];
    ull w2b[N2][N1 / 2];    // [j][p] = (W2[j][2p], W2[j][2p+1])
    ull w1b[N1][N0 / 2];    // [j][p] = (W1[j][2p], W1[j][2p+1])
};
__constant__ ConstTables cT;
__device__ ConstTables g_scratch;

__device__ __forceinline__ void swish2(ull z, ull& sw, ull& d) {
    float zl, zh;
    UNPACK2(zl, zh, z);
    float sl = __fdividef(1.0f, 1.0f + __expf(-zl));
    float sh = __fdividef(1.0f, 1.0f + __expf(-zh));
    ull s = packf(sl, sh);
    MUL2(sw, z, s);
    const ull ONE  = 0x3F8000003F800000ull;
    const ull NEG1 = 0xBF800000BF800000ull;
    ull oms;
    FMA2(oms, sw, NEG1, ONE);
    FMA2(d, s, oms, sw);
}

__global__ void prep_kernel(const float* __restrict__ W0, const float* __restrict__ b0,
                            const float* __restrict__ W1, const float* __restrict__ b1,
                            const float* __restrict__ W2, const float* __restrict__ b2,
                            const float* __restrict__ V)
{
    int i = blockIdx.x * blockDim.x + threadIdx.x;
    if (i < N0 / 2) {
        g_scratch.w0c[0][i] = packf(W0[(2 * i) * 2 + 0], W0[(2 * i + 1) * 2 + 0]);
        g_scratch.w0c[1][i] = packf(W0[(2 * i) * 2 + 1], W0[(2 * i + 1) * 2 + 1]);
        g_scratch.b0p[i]    = packf(b0[2 * i], b0[2 * i + 1]);
        g_scratch.b1p[i]    = packf(b1[2 * i], b1[2 * i + 1]);
    }
    if (i < N2 / 2) {
        g_scratch.b2p[i] = packf(b2[2 * i], b2[2 * i + 1]);
        g_scratch.vp[i]  = packf(V[2 * i], V[2 * i + 1]);
    }
    if (i < N0 * N1 / 2) {              // 512
        int k = i >> 4, p = i & 15;
        g_scratch.w1f[k][p] = packf(W1[(2 * p) * N0 + k], W1[(2 * p + 1) * N0 + k]);
        g_scratch.w1b[k][p] = packf(W1[k * N0 + 2 * p], W1[k * N0 + 2 * p + 1]);
    }
    if (i < N1 * N2 / 2) {              // 256
        int k = i >> 3, p = i & 7;
        g_scratch.w2f[k][p] = packf(W2[(2 * p) * N1 + k], W2[(2 * p + 1) * N1 + k]);
        int j = i >> 4, q = i & 15;
        g_scratch.w2b[j][q] = packf(W2[j * N1 + 2 * q], W2[j * N1 + 2 * q + 1]);
    }
}

#define NT 224   // threads per block

__global__ void __launch_bounds__(NT, 2) mlp_fused_kernel(
    const float4* __restrict__ in, float4* __restrict__ out, int Bp)
{
    extern __shared__ ull sd[];   // [64][NT]: row = e*32 + slot (slot<16: d0 pair, 16+p: d1 pair)
    const int t = blockIdx.x * blockDim.x + threadIdx.x;
    if (t >= Bp) return;          // no barriers in this kernel
    const int tid = threadIdx.x;

    const float4 xy = in[t];      // (x0, y0, x1, y1)
    ull X[2], Y[2];
    X[0] = packf(xy.x, xy.x);  Y[0] = packf(xy.y, xy.y);
    X[1] = packf(xy.z, xy.z);  Y[1] = packf(xy.w, xy.w);

    // ---- layer 0 fused into layer-1 accumulation (a0 never materialized) ----
    ull z1[2][N1 / 2];
    #pragma unroll
    for (int p = 0; p < N1 / 2; p++) { z1[0][p] = cT.b1p[p]; z1[1][p] = cT.b1p[p]; }

    #pragma unroll
    for (int p0 = 0; p0 < N0 / 2; p0++) {
        ull w0 = cT.w0c[0][p0], w1 = cT.w0c[1][p0], b = cT.b0p[p0];
        ull ak[2][2];   // [e][k in pair]
        #pragma unroll
        for (int e = 0; e < 2; e++) {
            ull z, sw, d;
            FMA2(z, X[e], w0, b);
            FMA2(z, Y[e], w1, z);
            swish2(z, sw, d);
            sd[(e * 32 + p0) * NT + tid] = d;          // d0 pair
            ak[e][0] = dup_lo(sw);
            ak[e][1] = dup_hi(sw);
        }
        const ulonglong2* wk0 = reinterpret_cast<const ulonglong2*>(cT.w1f[2 * p0]);
        const ulonglong2* wk1 = reinterpret_cast<const ulonglong2*>(cT.w1f[2 * p0 + 1]);
        #pragma unroll
        for (int q = 0; q < N1 / 4; q++) {
            ulonglong2 a2 = wk0[q];
            ulonglong2 b2v = wk1[q];
            FMA2(z1[0][2 * q],     ak[0][0], a2.x,  z1[0][2 * q]);
            FMA2(z1[1][2 * q],     ak[1][0], a2.x,  z1[1][2 * q]);
            FMA2(z1[0][2 * q + 1], ak[0][0], a2.y,  z1[0][2 * q + 1]);
            FMA2(z1[1][2 * q + 1], ak[1][0], a2.y,  z1[1][2 * q + 1]);
            FMA2(z1[0][2 * q],     ak[0][1], b2v.x, z1[0][2 * q]);
            FMA2(z1[1][2 * q],     ak[1][1], b2v.x, z1[1][2 * q]);
            FMA2(z1[0][2 * q + 1], ak[0][1], b2v.y, z1[0][2 * q + 1]);
            FMA2(z1[1][2 * q + 1], ak[1][1], b2v.y, z1[1][2 * q + 1]);
        }
    }

    // ---- layer-1 swish fused into layer-2 accumulation ----
    ull z2[2][N2 / 2];
    #pragma unroll
    for (int p = 0; p < N2 / 2; p++) { z2[0][p] = cT.b2p[p]; z2[1][p] = cT.b2p[p]; }

    #pragma unroll
    for (int p = 0; p < N1 / 2; p++) {
        ull ak[2][2];
        #pragma unroll
        for (int e = 0; e < 2; e++) {
            ull sw, d;
            swish2(z1[e][p], sw, d);
            sd[(e * 32 + 16 + p) * NT + tid] = d;      // d1 pair
            ak[e][0] = dup_lo(sw);
            ak[e][1] = dup_hi(sw);
        }
        const ulonglong2* wk0 = reinterpret_cast<const ulonglong2*>(cT.w2f[2 * p]);
        const ulonglong2* wk1 = reinterpret_cast<const ulonglong2*>(cT.w2f[2 * p + 1]);
        #pragma unroll
        for (int q = 0; q < N2 / 4; q++) {
            ulonglong2 a2 = wk0[q];
            ulonglong2 b2v = wk1[q];
            FMA2(z2[0][2 * q],     ak[0][0], a2.x,  z2[0][2 * q]);
            FMA2(z2[1][2 * q],     ak[1][0], a2.x,  z2[1][2 * q]);
            FMA2(z2[0][2 * q + 1], ak[0][0], a2.y,  z2[0][2 * q + 1]);
            FMA2(z2[1][2 * q + 1], ak[1][0], a2.y,  z2[1][2 * q + 1]);
            FMA2(z2[0][2 * q],     ak[0][1], b2v.x, z2[0][2 * q]);
            FMA2(z2[1][2 * q],     ak[1][1], b2v.x, z2[1][2 * q]);
            FMA2(z2[0][2 * q + 1], ak[0][1], b2v.y, z2[0][2 * q + 1]);
            FMA2(z2[1][2 * q + 1], ak[1][1], b2v.y, z2[1][2 * q + 1]);
        }
    }

    // ---- u2 = V .* dswish(z2) ----
    ull u2[2][N2 / 2];
    #pragma unroll
    for (int p = 0; p < N2 / 2; p++) {
        ull vpp = cT.vp[p];
        #pragma unroll
        for (int e = 0; e < 2; e++) {
            ull sw, d;
            swish2(z2[e][p], sw, d);
            MUL2(u2[e][p], vpp, d);
        }
    }

    // ---- backward: u1 = (W2^T u2) .* d1 ----
    ull u1[2][N1 / 2];
    #pragma unroll
    for (int p = 0; p < N1 / 2; p++) { u1[0][p] = 0ull; u1[1][p] = 0ull; }
    #pragma unroll
    for (int j = 0; j < N2; j++) {
        ull uj0 = (j & 1) ? dup_hi(u2[0][j >> 1]) : dup_lo(u2[0][j >> 1]);
        ull uj1 = (j & 1) ? dup_hi(u2[1][j >> 1]) : dup_lo(u2[1][j >> 1]);
        const ulonglong2* w = reinterpret_cast<const ulonglong2*>(cT.w2b[j]);
        #pragma unroll
        for (int q = 0; q < N1 / 4; q++) {
            ulonglong2 ww = w[q];
            FMA2(u1[0][2 * q],     uj0, ww.x, u1[0][2 * q]);
            FMA2(u1[1][2 * q],     uj1, ww.x, u1[1][2 * q]);
            FMA2(u1[0][2 * q + 1], uj0, ww.y, u1[0][2 * q + 1]);
            FMA2(u1[1][2 * q + 1], uj1, ww.y, u1[1][2 * q + 1]);
        }
    }
    #pragma unroll
    for (int p = 0; p < N1 / 2; p++) {
        #pragma unroll
        for (int e = 0; e < 2; e++) {
            ull d1 = sd[(e * 32 + 16 + p) * NT + tid];
            MUL2(u1[e][p], u1[e][p], d1);
        }
    }

    // ---- backward u0 fused into output (chunked: 8 accumulator pairs) ----
    ull o0[2], o1[2];
    o0[0] = o0[1] = o1[0] = o1[1] = 0ull;
    #pragma unroll
    for (int c = 0; c < 2; c++) {
        ull acc[2][N0 / 4];   // pairs p = 8c .. 8c+7
        #pragma unroll
        for (int pp = 0; pp < N0 / 4; pp++) { acc[0][pp] = 0ull; acc[1][pp] = 0ull; }
        #pragma unroll
        for (int j = 0; j < N1; j++) {
            ull uj0 = (j & 1) ? dup_hi(u1[0][j >> 1]) : dup_lo(u1[0][j >> 1]);
            ull uj1 = (j & 1) ? dup_hi(u1[1][j >> 1]) : dup_lo(u1[1][j >> 1]);
            const ulonglong2* w = reinterpret_cast<const ulonglong2*>(cT.w1b[j] + c * (N0 / 4));
            #pragma unroll
            for (int q = 0; q < N0 / 8; q++) {
                ulonglong2 ww = w[q];
                FMA2(acc[0][2 * q],     uj0, ww.x, acc[0][2 * q]);
                FMA2(acc[1][2 * q],     uj1, ww.x, acc[1][2 * q]);
                FMA2(acc[0][2 * q + 1], uj0, ww.y, acc[0][2 * q + 1]);
                FMA2(acc[1][2 * q + 1], uj1, ww.y, acc[1][2 * q + 1]);
            }
        }
        #pragma unroll
        for (int pp = 0; pp < N0 / 4; pp++) {
            int p = c * (N0 / 4) + pp;
            ull wa = cT.w0c[0][p], wb = cT.w0c[1][p];
            #pragma unroll
            for (int e = 0; e < 2; e++) {
                ull d0 = sd[(e * 32 + p) * NT + tid];
                ull u0;
                MUL2(u0, acc[e][pp], d0);
                FMA2(o0[e], u0, wa, o0[e]);
                FMA2(o1[e], u0, wb, o1[e]);
            }
        }
    }

    float r00l, r00h, r01l, r01h, r10l, r10h, r11l, r11h;
    UNPACK2(r00l, r00h, o0[0]);
    UNPACK2(r01l, r01h, o1[0]);
    UNPACK2(r10l, r10h, o0[1]);
    UNPACK2(r11l, r11h, o1[1]);
    out[t] = make_float4(r00l + r00h, r01l + r01h, r10l + r10h, r11l + r11h);
}

extern "C" void kernel_launch(void* const* d_in, const int* in_sizes, int n_in,
                              void* d_out, int out_size)
{
    prep_kernel<<<8, 128>>>((const float*)d_in[1], (const float*)d_in[2],
                            (const float*)d_in[3], (const float*)d_in[4],
                            (const float*)d_in[5], (const float*)d_in[6],
                            (const float*)d_in[7]);

    void *dst = nullptr, *src = nullptr;
    cudaGetSymbolAddress(&dst, cT);
    cudaGetSymbolAddress(&src, g_scratch);
    cudaMemcpyAsync(dst, src, sizeof(ConstTables), cudaMemcpyDeviceToDevice, 0);

    const int B  = in_sizes[0] / 2;   // inputs is [B, 2]
    const int Bp = B / 2;
    const int blocks = (Bp + NT - 1) / NT;
    const int smem = 64 * NT * sizeof(ull);   // 112 KB dynamic

    cudaFuncSetAttribute(mlp_fused_kernel, cudaFuncAttributeMaxDynamicSharedMemorySize, smem);
    mlp_fused_kernel<<<blocks, NT, smem>>>(
        (const float4*)d_in[0], (float4*)d_out, Bp);
}